// round 8
// baseline (speedup 1.0000x reference)
#include <cuda_runtime.h>
#include <math.h>

#define N_ANT 64
#define HID   128
#define AP    136   // activation pitch: AP/2 % 16 == 4 -> A-pair LDS.64 conflict-free
#define WP2   132   // staged-weight pitch in float2 units (conflict-free B-pair loads)
#define WCH2  (16 * WP2)   // float2 elems per 32-k chunk per weight
#define SP    72    // score pitch: SP/2 % 16 == 4 (P-pairs), softmax conflict-free
#define NTH   512

typedef unsigned long long u64;

__device__ __forceinline__ unsigned cvt_tf32(float v) {
    unsigned r; asm("cvt.rna.tf32.f32 %0, %1;" : "=r"(r) : "f"(v)); return r;
}
__device__ __forceinline__ void mma8(float& d0, float& d1, float& d2, float& d3,
                                     unsigned a0, unsigned a1, unsigned a2, unsigned a3,
                                     unsigned b0, unsigned b1) {
    asm("mma.sync.aligned.m16n8k8.row.col.f32.tf32.tf32.f32 "
        "{%0,%1,%2,%3},{%4,%5,%6,%7},{%8,%9},{%0,%1,%2,%3};"
        : "+f"(d0), "+f"(d1), "+f"(d2), "+f"(d3)
        : "r"(a0), "r"(a1), "r"(a2), "r"(a3), "r"(b0), "r"(b1));
}
__device__ __forceinline__ float f4c(const float4& v, int c) {
    return (c == 0) ? v.x : (c == 1) ? v.y : (c == 2) ? v.z : v.w;
}
// Per-octet column permutation: logical k -> storage slot, so mma A/B k-pairs
// (k, k+4) land adjacent (slots 2(k&3), 2(k&3)+1).
__device__ __forceinline__ int slot8(int k) { return ((k & 3) << 1) | ((k >> 2) & 1); }
__device__ __forceinline__ int pcol(int k)  { return (k & ~7) | slot8(k & 7); }
__device__ __forceinline__ int lcol(int s)  { return (s & ~7) | (((s & 1) << 2) | ((s >> 1) & 3)); }

struct __align__(16) SmemLayout {
    float  B0[N_ANT * AP];
    float  B1[N_ANT * AP];
    float  B2[N_ANT * AP];
    float  B3[N_ANT * AP];
    float2 Ws[3 * WCH2];        // pre-paired tf32 weights, up to 3 fused
    float  Ss[N_ANT * SP];
    u64    mb[N_ANT];
};

#define EPI_PLAIN  0
#define EPI_RELU   1
#define EPI_SIGADD 2   // C = sigmoid(acc + T)
#define EPI_TANHN  3   // C = tanh(T + R*acc)

// Fused multi-weight GEMM on tf32 mma.sync with pair-packed operands.
// C[w][64][128] = epi( A[64][KDIM] @ Wg[w][128][KDIM]^T + bg[w] ), A/C permuted layout.
template <int KDIM, int NW>
__device__ __noinline__ void gemm_mma(
    const float* __restrict__ A,
    const float* const* Wg, const float* const* bg,
    float* const* C, const float* const* T, const float* R,
    float2* __restrict__ Ws, int tid, int mode)
{
    const int lane = tid & 31;
    const int wrp  = tid >> 5;
    const int g    = lane >> 2;
    const int tg   = lane & 3;
    const int mi   = wrp & 3;
    const int ni   = wrp >> 2;
    const int r0   = mi * 16 + g;
    const int r1   = r0 + 8;
    const int js   = tid & 127;          // weight output-row for staging
    const int kq   = (tid >> 7) * 8;     // k-octet base within chunk (0,8,16,24)
    const int oct4 = (kq >> 3) * 4;      // pairIdx base for this octet

    const float* Wp[NW]; const float* bp[NW]; float* Cp[NW]; const float* Tp[NW];
#pragma unroll
    for (int w = 0; w < NW; w++) { Wp[w] = Wg[w]; bp[w] = bg[w]; Cp[w] = C[w]; Tp[w] = T[w]; }

    // D fragments, bias-initialized (logical cols j = ni*32+nt*8+2tg, j+1)
    float d[NW][4][4];
#pragma unroll
    for (int w = 0; w < NW; w++)
#pragma unroll
        for (int nt = 0; nt < 4; nt++) {
            const int j = ni * 32 + nt * 8 + 2 * tg;
            const float bb0 = bp[w][j];
            const float bb1 = bp[w][j + 1];
            d[w][nt][0] = bb0; d[w][nt][1] = bb1;
            d[w][nt][2] = bb0; d[w][nt][3] = bb1;
        }

    float4 stg[NW][2];
#pragma unroll
    for (int w = 0; w < NW; w++) {
        const float* src = Wp[w] + js * KDIM + kq;
        stg[w][0] = *reinterpret_cast<const float4*>(src);
        stg[w][1] = *reinterpret_cast<const float4*>(src + 4);
    }

    constexpr int NC = KDIM / 32;
#pragma unroll 1
    for (int c = 0; c < NC; c++) {
        __syncthreads();                       // previous users of Ws done
#pragma unroll
        for (int w = 0; w < NW; w++) {
#pragma unroll
            for (int e = 0; e < 4; e++) {      // pair (k=kq+e, k=kq+e+4) -> one STS.64
                const float lo = f4c(stg[w][0], e);
                const float hi = f4c(stg[w][1], e);
                Ws[w * WCH2 + (oct4 + e) * WP2 + js] =
                    make_float2(__uint_as_float(cvt_tf32(lo)), __uint_as_float(cvt_tf32(hi)));
            }
        }
        __syncthreads();
        if (c + 1 < NC) {                      // prefetch next chunk under compute
#pragma unroll
            for (int w = 0; w < NW; w++) {
                const float* src = Wp[w] + js * KDIM + (c + 1) * 32 + kq;
                stg[w][0] = *reinterpret_cast<const float4*>(src);
                stg[w][1] = *reinterpret_cast<const float4*>(src + 4);
            }
        }
#pragma unroll
        for (int ks = 0; ks < 4; ks++) {       // four k8 steps per chunk
            const int kk = c * 32 + ks * 8;
            const float2 pa0 = *reinterpret_cast<const float2*>(A + r0 * AP + kk + 2 * tg);
            const float2 pa1 = *reinterpret_cast<const float2*>(A + r1 * AP + kk + 2 * tg);
            const unsigned a0 = cvt_tf32(pa0.x);
            const unsigned a2 = cvt_tf32(pa0.y);
            const unsigned a1 = cvt_tf32(pa1.x);
            const unsigned a3 = cvt_tf32(pa1.y);
#pragma unroll
            for (int w = 0; w < NW; w++) {
#pragma unroll
                for (int nt = 0; nt < 4; nt++) {
                    const int n = ni * 32 + nt * 8 + g;
                    const float2 pb = Ws[w * WCH2 + (ks * 4 + tg) * WP2 + n];
                    mma8(d[w][nt][0], d[w][nt][1], d[w][nt][2], d[w][nt][3],
                         a0, a1, a2, a3,
                         __float_as_uint(pb.x), __float_as_uint(pb.y));
                }
            }
        }
    }
    __syncthreads();   // all A/Ws reads done -> safe to write C even if C aliases A

#pragma unroll
    for (int w = 0; w < NW; w++) {
#pragma unroll
        for (int nt = 0; nt < 4; nt++) {
            const int oct = ni * 32 + nt * 8;
            const int s0  = oct + slot8(2 * tg);
            const int s1  = oct + slot8(2 * tg + 1);
            float v0 = d[w][nt][0], v1 = d[w][nt][1];
            float v2 = d[w][nt][2], v3 = d[w][nt][3];
            if (mode == EPI_RELU) {
                v0 = fmaxf(v0, 0.f); v1 = fmaxf(v1, 0.f);
                v2 = fmaxf(v2, 0.f); v3 = fmaxf(v3, 0.f);
            } else if (mode == EPI_SIGADD) {
                v0 += Tp[w][r0 * AP + s0]; v1 += Tp[w][r0 * AP + s1];
                v2 += Tp[w][r1 * AP + s0]; v3 += Tp[w][r1 * AP + s1];
                v0 = 1.f / (1.f + __expf(-v0)); v1 = 1.f / (1.f + __expf(-v1));
                v2 = 1.f / (1.f + __expf(-v2)); v3 = 1.f / (1.f + __expf(-v3));
            } else if (mode == EPI_TANHN) {
                v0 = tanhf(Tp[w][r0 * AP + s0] + R[r0 * AP + s0] * v0);
                v1 = tanhf(Tp[w][r0 * AP + s1] + R[r0 * AP + s1] * v1);
                v2 = tanhf(Tp[w][r1 * AP + s0] + R[r1 * AP + s0] * v2);
                v3 = tanhf(Tp[w][r1 * AP + s1] + R[r1 * AP + s1] * v3);
            }
            Cp[w][r0 * AP + s0] = v0; Cp[w][r0 * AP + s1] = v1;
            Cp[w][r1 * AP + s0] = v2; Cp[w][r1 * AP + s1] = v3;
        }
    }
    __syncthreads();
}

// Masked MHA core on tf32 mma with pair-packed operands.
__device__ __noinline__ void attention_mma(
    const float* __restrict__ Q, const float* __restrict__ K,
    const float* __restrict__ V, float* __restrict__ O,
    float* __restrict__ Ss, const u64* __restrict__ mb, int tid)
{
    const float scale = 0.17677669529663687f;  // 1/sqrt(32)
    const int lane = tid & 31;
    const int wrp  = tid >> 5;
    const int g    = lane >> 2;
    const int tg   = lane & 3;
    const int mi   = wrp & 3;
    const int r0   = mi * 16 + g;
    const int r1   = r0 + 8;
#pragma unroll 1
    for (int h = 0; h < 4; h++) {
        const int c0 = h * 32;
        // ---- scores: S = scale * Q_h @ K_h^T   (M=64, N=64, K=32) ----
        {
            const int nj = wrp >> 2;             // 2 n8-tiles at nj*16
            float sd[2][4] = {{0.f,0.f,0.f,0.f},{0.f,0.f,0.f,0.f}};
#pragma unroll
            for (int ks = 0; ks < 4; ks++) {
                const int kk = c0 + ks * 8;
                const float2 pa0 = *reinterpret_cast<const float2*>(Q + r0 * AP + kk + 2 * tg);
                const float2 pa1 = *reinterpret_cast<const float2*>(Q + r1 * AP + kk + 2 * tg);
                const unsigned a0 = cvt_tf32(pa0.x);
                const unsigned a2 = cvt_tf32(pa0.y);
                const unsigned a1 = cvt_tf32(pa1.x);
                const unsigned a3 = cvt_tf32(pa1.y);
#pragma unroll
                for (int u = 0; u < 2; u++) {
                    const int n0 = nj * 16 + u * 8;
                    const float2 pb = *reinterpret_cast<const float2*>(
                        K + (n0 + g) * AP + kk + 2 * tg);
                    mma8(sd[u][0], sd[u][1], sd[u][2], sd[u][3],
                         a0, a1, a2, a3, cvt_tf32(pb.x), cvt_tf32(pb.y));
                }
            }
#pragma unroll
            for (int u = 0; u < 2; u++) {
                const int oct = nj * 16 + u * 8;
                const int s0  = oct + slot8(2 * tg);
                const int s1  = oct + slot8(2 * tg + 1);
                Ss[r0 * SP + s0] = sd[u][0] * scale;
                Ss[r0 * SP + s1] = sd[u][1] * scale;
                Ss[r1 * SP + s0] = sd[u][2] * scale;
                Ss[r1 * SP + s1] = sd[u][3] * scale;
            }
        }
        __syncthreads();
        // ---- masked softmax over keys (8 threads per row; slots permuted) ----
        {
            const int t = tid >> 3;
            const int q = tid & 7;
            const u64 bits = mb[t];
            float mx = -1e30f;
            for (int sidx = q; sidx < N_ANT; sidx += 8) {
                const int m = lcol(sidx);
                if ((bits >> m) & 1ULL) mx = fmaxf(mx, Ss[t * SP + sidx]);
            }
            mx = fmaxf(mx, __shfl_xor_sync(0xffffffffu, mx, 1));
            mx = fmaxf(mx, __shfl_xor_sync(0xffffffffu, mx, 2));
            mx = fmaxf(mx, __shfl_xor_sync(0xffffffffu, mx, 4));
            float sum = 0.f;
            for (int sidx = q; sidx < N_ANT; sidx += 8) {
                const int m = lcol(sidx);
                const float p = ((bits >> m) & 1ULL) ? __expf(Ss[t * SP + sidx] - mx) : 0.f;
                Ss[t * SP + sidx] = p;
                sum += p;
            }
            sum += __shfl_xor_sync(0xffffffffu, sum, 1);
            sum += __shfl_xor_sync(0xffffffffu, sum, 2);
            sum += __shfl_xor_sync(0xffffffffu, sum, 4);
            const float rinv = 1.f / sum;
            for (int sidx = q; sidx < N_ANT; sidx += 8) Ss[t * SP + sidx] *= rinv;
        }
        __syncthreads();
        // ---- O[:, c0:c0+32] = P @ V[:, c0:c0+32]   (M=64, N=32, K=64) ----
        {
            const int nt  = wrp >> 2;            // 1 n8-tile per warp
            const int svg = c0 + nt * 8 + slot8(g);  // V storage col for logical n0+g
            float od[4] = {0.f, 0.f, 0.f, 0.f};
#pragma unroll
            for (int ks = 0; ks < 8; ks++) {
                const int kk = ks * 8;
                const float2 pa0 = *reinterpret_cast<const float2*>(Ss + r0 * SP + kk + 2 * tg);
                const float2 pa1 = *reinterpret_cast<const float2*>(Ss + r1 * SP + kk + 2 * tg);
                const unsigned b0 = cvt_tf32(V[(kk + tg) * AP + svg]);
                const unsigned b1 = cvt_tf32(V[(kk + tg + 4) * AP + svg]);
                mma8(od[0], od[1], od[2], od[3],
                     cvt_tf32(pa0.x), cvt_tf32(pa1.x), cvt_tf32(pa0.y), cvt_tf32(pa1.y),
                     b0, b1);
            }
            const int oct = c0 + nt * 8;
            const int s0  = oct + slot8(2 * tg);
            const int s1  = oct + slot8(2 * tg + 1);
            O[r0 * AP + s0] = od[0]; O[r0 * AP + s1] = od[1];
            O[r1 * AP + s0] = od[2]; O[r1 * AP + s1] = od[3];
        }
        __syncthreads();
    }
}

__global__ void __launch_bounds__(NTH, 1) drgn_kernel(
    const float* __restrict__ x, const int* __restrict__ mask,
    const float* __restrict__ hs,
    const float* __restrict__ enc_w, const float* __restrict__ enc_b,
    const float* __restrict__ q1_w, const float* __restrict__ q1_b,
    const float* __restrict__ k1_w, const float* __restrict__ k1_b,
    const float* __restrict__ v1_w, const float* __restrict__ v1_b,
    const float* __restrict__ o1_w, const float* __restrict__ o1_b,
    const float* __restrict__ q2_w, const float* __restrict__ q2_b,
    const float* __restrict__ k2_w, const float* __restrict__ k2_b,
    const float* __restrict__ v2_w, const float* __restrict__ v2_b,
    const float* __restrict__ o2_w, const float* __restrict__ o2_b,
    const float* __restrict__ w_ih, const float* __restrict__ w_hh,
    const float* __restrict__ b_ih, const float* __restrict__ b_hh,
    const float* __restrict__ lin_w, const float* __restrict__ lin_b,
    float* __restrict__ qs_out, float* __restrict__ h3_out, int act)
{
    extern __shared__ char smem_raw[];
    SmemLayout* s = reinterpret_cast<SmemLayout*>(smem_raw);
    const int tid = threadIdx.x;
    const int b   = blockIdx.x;

    // ---- load x tile (permuted cols) and mask bitmap ----
    {
        const float* xb = x + (size_t)b * (N_ANT * 64);
        for (int idx = tid; idx < N_ANT * 64; idx += NTH) {
            const int row = idx >> 6, c = idx & 63;
            s->B0[row * AP + pcol(c)] = xb[idx];
        }
        if (tid < N_ANT) {
            const int* mrow = mask + ((size_t)b * N_ANT + tid) * N_ANT;
            u64 bits = 0ULL;
            for (int m = 0; m < N_ANT; m++)
                bits |= (u64)(mrow[m] != 0) << m;
            s->mb[tid] = bits;
        }
    }
    // (gemm_mma opens with __syncthreads -> orders the fills above)

    // ---- encoder: xe = relu(x @ enc_w^T) -> B1 ----
    {
        const float* W[1] = {enc_w}; const float* B[1] = {enc_b};
        float* Cc[1] = {s->B1};      const float* Tt[1] = {nullptr};
        gemm_mma<64, 1>(s->B0, W, B, Cc, Tt, nullptr, s->Ws, tid, EPI_RELU);
    }

    // ---- MHA layer 1: fused QKV from xe (B1) ----
    {
        const float* W[3] = {q1_w, k1_w, v1_w};
        const float* B[3] = {q1_b, k1_b, v1_b};
        float* Cc[3] = {s->B0, s->B2, s->B3};
        const float* Tt[3] = {nullptr, nullptr, nullptr};
        gemm_mma<128, 3>(s->B1, W, B, Cc, Tt, nullptr, s->Ws, tid, EPI_RELU);
    }
    attention_mma(s->B0, s->B2, s->B3, s->B1, s->Ss, s->mb, tid);
    {
        const float* W[1] = {o1_w}; const float* B[1] = {o1_b};
        float* Cc[1] = {s->B0};     const float* Tt[1] = {nullptr};
        gemm_mma<128, 1>(s->B1, W, B, Cc, Tt, nullptr, s->Ws, tid, EPI_RELU);  // h1 -> B0
    }

    // ---- MHA layer 2: fused QKV from h1 (B0) ----
    {
        const float* W[3] = {q2_w, k2_w, v2_w};
        const float* B[3] = {q2_b, k2_b, v2_b};
        float* Cc[3] = {s->B1, s->B2, s->B3};
        const float* Tt[3] = {nullptr, nullptr, nullptr};
        gemm_mma<128, 3>(s->B0, W, B, Cc, Tt, nullptr, s->Ws, tid, EPI_RELU);
    }
    attention_mma(s->B1, s->B2, s->B3, s->B0, s->Ss, s->mb, tid);
    {
        const float* W[1] = {o2_w}; const float* B[1] = {o2_b};
        float* Cc[1] = {s->B1};     const float* Tt[1] = {nullptr};
        gemm_mma<128, 1>(s->B0, W, B, Cc, Tt, nullptr, s->Ws, tid, EPI_RELU);  // h2 -> B1
    }

    // ---- load previous hidden state (permuted cols) -> B2 ----
    {
        const float* hb = hs + (size_t)b * (N_ANT * HID);
        for (int idx = tid; idx < N_ANT * HID; idx += NTH) {
            const int row = idx >> 7, c = idx & 127;
            s->B2[row * AP + pcol(c)] = hb[idx];
        }
    }

    // ---- GRU cell: h2 (B1), h (B2) ----
    {   // i_r -> B0, i_z -> B3  (fused, plain)
        const float* W[2] = {w_ih, w_ih + 128 * HID};
        const float* B[2] = {b_ih, b_ih + 128};
        float* Cc[2] = {s->B0, s->B3};
        const float* Tt[2] = {nullptr, nullptr};
        gemm_mma<128, 2>(s->B1, W, B, Cc, Tt, nullptr, s->Ws, tid, EPI_PLAIN);
    }
    {   // r = sig(i_r + h_r) -> B0 ; z = sig(i_z + h_z) -> B3  (fused)
        const float* W[2] = {w_hh, w_hh + 128 * HID};
        const float* B[2] = {b_hh, b_hh + 128};
        float* Cc[2] = {s->B0, s->B3};
        const float* Tt[2] = {s->B0, s->B3};
        gemm_mma<128, 2>(s->B2, W, B, Cc, Tt, nullptr, s->Ws, tid, EPI_SIGADD);
    }
    {   // i_n -> B1 (in place over h2; safe: sync precedes epilogue writes)
        const float* W[1] = {w_ih + 256 * HID}; const float* B[1] = {b_ih + 256};
        float* Cc[1] = {s->B1}; const float* Tt[1] = {nullptr};
        gemm_mma<128, 1>(s->B1, W, B, Cc, Tt, nullptr, s->Ws, tid, EPI_PLAIN);
    }
    {   // n = tanh(i_n + r * h_n) -> B1
        const float* W[1] = {w_hh + 256 * HID}; const float* B[1] = {b_hh + 256};
        float* Cc[1] = {s->B1}; const float* Tt[1] = {s->B1};
        gemm_mma<128, 1>(s->B2, W, B, Cc, Tt, s->B0, s->Ws, tid, EPI_TANHN);
    }

    // ---- h3 = (1-z)*n + z*h ; write h3 (logical order) and keep in B1 ----
    {
        float* h3b = h3_out + (size_t)b * (N_ANT * HID);
        for (int idx = tid; idx < N_ANT * HID; idx += NTH) {
            const int row = idx >> 7, c = idx & 127;
            const int off = row * AP + pcol(c);
            const float z  = s->B3[off];
            const float h3 = (1.f - z) * s->B1[off] + z * s->B2[off];
            s->B1[off] = h3;
            h3b[idx]   = h3;
        }
    }
    __syncthreads();

    // ---- qs = h3 @ lin_w^T + lin_b (tiny tail; permuted-aware) ----
    {
        float* qb = qs_out + (size_t)b * (N_ANT * act);
        for (int idx = tid; idx < N_ANT * act; idx += NTH) {
            const int t = idx / act;
            const int a = idx - t * act;
            const float* wr = lin_w + a * HID;
            const float* hr = s->B1 + t * AP;
            float sacc = lin_b[a];
#pragma unroll 8
            for (int k = 0; k < HID; k++) sacc = fmaf(hr[pcol(k)], wr[k], sacc);
            qb[idx] = sacc;
        }
    }
}

extern "C" void kernel_launch(void* const* d_in, const int* in_sizes, int n_in,
                              void* d_out, int out_size)
{
    const float* x     = (const float*)d_in[0];
    const int*   mask  = (const int*)  d_in[1];
    const float* hs    = (const float*)d_in[2];
    const float* enc_w = (const float*)d_in[3];
    const float* enc_b = (const float*)d_in[4];
    const float* q1_w  = (const float*)d_in[5];
    const float* q1_b  = (const float*)d_in[6];
    const float* k1_w  = (const float*)d_in[7];
    const float* k1_b  = (const float*)d_in[8];
    const float* v1_w  = (const float*)d_in[9];
    const float* v1_b  = (const float*)d_in[10];
    const float* o1_w  = (const float*)d_in[11];
    const float* o1_b  = (const float*)d_in[12];
    const float* q2_w  = (const float*)d_in[13];
    const float* q2_b  = (const float*)d_in[14];
    const float* k2_w  = (const float*)d_in[15];
    const float* k2_b  = (const float*)d_in[16];
    const float* v2_w  = (const float*)d_in[17];
    const float* v2_b  = (const float*)d_in[18];
    const float* o2_w  = (const float*)d_in[19];
    const float* o2_b  = (const float*)d_in[20];
    const float* w_ih  = (const float*)d_in[21];
    const float* w_hh  = (const float*)d_in[22];
    const float* b_ih  = (const float*)d_in[23];
    const float* b_hh  = (const float*)d_in[24];
    const float* lin_w = (const float*)d_in[25];
    const float* lin_b = (const float*)d_in[26];

    const int bs  = in_sizes[0] / (N_ANT * 64);
    const int act = in_sizes[25] / HID;  // 20

    float* qs = (float*)d_out;
    float* h3 = qs + (size_t)bs * N_ANT * act;

    const int smem_bytes = (int)sizeof(SmemLayout);
    cudaFuncSetAttribute(drgn_kernel, cudaFuncAttributeMaxDynamicSharedMemorySize, smem_bytes);

    drgn_kernel<<<bs, NTH, smem_bytes>>>(
        x, mask, hs, enc_w, enc_b,
        q1_w, q1_b, k1_w, k1_b, v1_w, v1_b, o1_w, o1_b,
        q2_w, q2_b, k2_w, k2_b, v2_w, v2_b, o2_w, o2_b,
        w_ih, w_hh, b_ih, b_hh, lin_w, lin_b,
        qs, h3, act);
}

// round 11
// speedup vs baseline: 1.4705x; 1.4705x over previous
#include <cuda_runtime.h>
#include <math.h>

#define N_ANT 64
#define HID   128
#define AP    132   // activation pitch: (4g+tg) bank map -> A-fragment LDS conflict-free
#define WPF   132   // full-weight pitch: B-fragment loads conflict-free
#define SP    68    // score pitch
#define NTH   512

typedef unsigned long long u64;

__device__ __forceinline__ unsigned cvt_tf32(float v) {
    unsigned r; asm("cvt.rna.tf32.f32 %0, %1;" : "=r"(r) : "f"(v)); return r;
}
__device__ __forceinline__ void mma8(float& d0, float& d1, float& d2, float& d3,
                                     unsigned a0, unsigned a1, unsigned a2, unsigned a3,
                                     unsigned b0, unsigned b1) {
    asm("mma.sync.aligned.m16n8k8.row.col.f32.tf32.tf32.f32 "
        "{%0,%1,%2,%3},{%4,%5,%6,%7},{%8,%9},{%0,%1,%2,%3};"
        : "+f"(d0), "+f"(d1), "+f"(d2), "+f"(d3)
        : "r"(a0), "r"(a1), "r"(a2), "r"(a3), "r"(b0), "r"(b1));
}

struct __align__(16) SmemLayout {
    float B0[N_ANT * AP];
    float B1[N_ANT * AP];
    float B2[N_ANT * AP];
    float B3[N_ANT * AP];
    float Ws[HID * WPF];     // one full weight matrix [128 x <=128], pitch WPF
    float Ss[N_ANT * SP];
    u64   mb[N_ANT];
};

#define EPI_PLAIN  0
#define EPI_RELU   1
#define EPI_SIGADD 2   // C = sigmoid(acc + T)
#define EPI_TANHN  3   // C = tanh(T + R*acc)

// C[64][128] = epi( A[64][KDIM] @ Wg[128][KDIM]^T + bg ), tf32 mma.sync.
// Full weight staged to smem via coalesced LDG.128 -> STS.128; no k-chunking.
// Warp tiling: mi=wrp&3 -> rows mi*16..+15 ; ni=wrp>>2 -> cols ni*32..+31.
template <int KDIM>
__device__ __noinline__ void gemm_one(
    const float* __restrict__ A, const float* __restrict__ Wg,
    const float* __restrict__ bg, float* __restrict__ C,
    const float* __restrict__ T, const float* __restrict__ R,
    float* __restrict__ Ws, int tid, int mode)
{
    const int lane = tid & 31;
    const int wrp  = tid >> 5;
    const int g    = lane >> 2;
    const int tg   = lane & 3;
    const int mi   = wrp & 3;
    const int ni   = wrp >> 2;
    const int r0   = mi * 16 + g;
    const int r1   = r0 + 8;

    // ---- stage full weight, coalesced (Ws is free: caller's trailing sync) ----
    constexpr int C4 = KDIM / 4;                 // float4 per weight row
    constexpr int IT = (HID * KDIM / 4) / NTH;   // float4 per thread (8 or 4)
    {
        float4 tmp[IT];
#pragma unroll
        for (int i = 0; i < IT; i++) {
            const int f   = tid + i * NTH;
            const int row = f / C4;
            const int c4  = f - row * C4;
            tmp[i] = *reinterpret_cast<const float4*>(Wg + row * KDIM + c4 * 4);
        }
#pragma unroll
        for (int i = 0; i < IT; i++) {
            const int f   = tid + i * NTH;
            const int row = f / C4;
            const int c4  = f - row * C4;
            *reinterpret_cast<float4*>(Ws + row * WPF + c4 * 4) = tmp[i];
        }
    }

    // D fragments, bias-initialized: cols j = ni*32+nt*8+2tg, j+1; rows r0, r1
    float d[4][4];
#pragma unroll
    for (int nt = 0; nt < 4; nt++) {
        const float2 b2 = *reinterpret_cast<const float2*>(bg + ni * 32 + nt * 8 + 2 * tg);
        d[nt][0] = b2.x; d[nt][1] = b2.y;
        d[nt][2] = b2.x; d[nt][3] = b2.y;
    }

    __syncthreads();   // Ws staged; also orders prior writes to A

#pragma unroll 4
    for (int ks = 0; ks < KDIM / 8; ks++) {
        const int kk = ks * 8;
        const unsigned a0 = cvt_tf32(A[r0 * AP + kk + tg]);
        const unsigned a1 = cvt_tf32(A[r1 * AP + kk + tg]);
        const unsigned a2 = cvt_tf32(A[r0 * AP + kk + tg + 4]);
        const unsigned a3 = cvt_tf32(A[r1 * AP + kk + tg + 4]);
#pragma unroll
        for (int nt = 0; nt < 4; nt++) {
            const int n = ni * 32 + nt * 8 + g;
            const unsigned b0 = cvt_tf32(Ws[n * WPF + kk + tg]);
            const unsigned b1 = cvt_tf32(Ws[n * WPF + kk + tg + 4]);
            mma8(d[nt][0], d[nt][1], d[nt][2], d[nt][3], a0, a1, a2, a3, b0, b1);
        }
    }
    __syncthreads();   // all A/Ws reads done -> safe to write C even if C aliases A

#pragma unroll
    for (int nt = 0; nt < 4; nt++) {
        const int j = ni * 32 + nt * 8 + 2 * tg;
        float v0 = d[nt][0], v1 = d[nt][1];
        float v2 = d[nt][2], v3 = d[nt][3];
        if (mode == EPI_RELU) {
            v0 = fmaxf(v0, 0.f); v1 = fmaxf(v1, 0.f);
            v2 = fmaxf(v2, 0.f); v3 = fmaxf(v3, 0.f);
        } else if (mode == EPI_SIGADD) {
            v0 += T[r0 * AP + j]; v1 += T[r0 * AP + j + 1];
            v2 += T[r1 * AP + j]; v3 += T[r1 * AP + j + 1];
            v0 = 1.f / (1.f + __expf(-v0)); v1 = 1.f / (1.f + __expf(-v1));
            v2 = 1.f / (1.f + __expf(-v2)); v3 = 1.f / (1.f + __expf(-v3));
        } else if (mode == EPI_TANHN) {
            v0 = tanhf(T[r0 * AP + j]     + R[r0 * AP + j]     * v0);
            v1 = tanhf(T[r0 * AP + j + 1] + R[r0 * AP + j + 1] * v1);
            v2 = tanhf(T[r1 * AP + j]     + R[r1 * AP + j]     * v2);
            v3 = tanhf(T[r1 * AP + j + 1] + R[r1 * AP + j + 1] * v3);
        }
        *reinterpret_cast<float2*>(C + r0 * AP + j) = make_float2(v0, v1);
        *reinterpret_cast<float2*>(C + r1 * AP + j) = make_float2(v2, v3);
    }
    __syncthreads();
}

// Masked MHA core on tf32 mma (identical to the measured-best R6 version).
__device__ __noinline__ void attention_mma(
    const float* __restrict__ Q, const float* __restrict__ K,
    const float* __restrict__ V, float* __restrict__ O,
    float* __restrict__ Ss, const u64* __restrict__ mb, int tid)
{
    const float scale = 0.17677669529663687f;  // 1/sqrt(32)
    const int lane = tid & 31;
    const int wrp  = tid >> 5;
    const int g    = lane >> 2;
    const int tg   = lane & 3;
    const int mi   = wrp & 3;
    const int r0   = mi * 16 + g;
    const int r1   = r0 + 8;
#pragma unroll 1
    for (int h = 0; h < 4; h++) {
        const int c0 = h * 32;
        // ---- scores: S = scale * Q_h @ K_h^T   (M=64, N=64, K=32) ----
        {
            const int nj = wrp >> 2;             // 2 n8-tiles at nj*16
            float sd[2][4] = {{0.f,0.f,0.f,0.f},{0.f,0.f,0.f,0.f}};
#pragma unroll
            for (int ks = 0; ks < 4; ks++) {
                const int kk = c0 + ks * 8;
                const unsigned a0 = cvt_tf32(Q[r0 * AP + kk + tg]);
                const unsigned a1 = cvt_tf32(Q[r1 * AP + kk + tg]);
                const unsigned a2 = cvt_tf32(Q[r0 * AP + kk + tg + 4]);
                const unsigned a3 = cvt_tf32(Q[r1 * AP + kk + tg + 4]);
#pragma unroll
                for (int u = 0; u < 2; u++) {
                    const int n0 = nj * 16 + u * 8;
                    const unsigned b0 = cvt_tf32(K[(n0 + g) * AP + kk + tg]);
                    const unsigned b1 = cvt_tf32(K[(n0 + g) * AP + kk + tg + 4]);
                    mma8(sd[u][0], sd[u][1], sd[u][2], sd[u][3], a0, a1, a2, a3, b0, b1);
                }
            }
#pragma unroll
            for (int u = 0; u < 2; u++) {
                const int n = nj * 16 + u * 8 + 2 * tg;
                Ss[r0 * SP + n]     = sd[u][0] * scale;
                Ss[r0 * SP + n + 1] = sd[u][1] * scale;
                Ss[r1 * SP + n]     = sd[u][2] * scale;
                Ss[r1 * SP + n + 1] = sd[u][3] * scale;
            }
        }
        __syncthreads();
        // ---- masked softmax over keys (8 threads per row) ----
        {
            const int t = tid >> 3;
            const int q = tid & 7;
            const u64 bits = mb[t];
            float mx = -1e30f;
            for (int m = q; m < N_ANT; m += 8)
                if ((bits >> m) & 1ULL) mx = fmaxf(mx, Ss[t * SP + m]);
            mx = fmaxf(mx, __shfl_xor_sync(0xffffffffu, mx, 1));
            mx = fmaxf(mx, __shfl_xor_sync(0xffffffffu, mx, 2));
            mx = fmaxf(mx, __shfl_xor_sync(0xffffffffu, mx, 4));
            float sum = 0.f;
            for (int m = q; m < N_ANT; m += 8) {
                const float p = ((bits >> m) & 1ULL) ? __expf(Ss[t * SP + m] - mx) : 0.f;
                Ss[t * SP + m] = p;
                sum += p;
            }
            sum += __shfl_xor_sync(0xffffffffu, sum, 1);
            sum += __shfl_xor_sync(0xffffffffu, sum, 2);
            sum += __shfl_xor_sync(0xffffffffu, sum, 4);
            const float rinv = 1.f / sum;
            for (int m = q; m < N_ANT; m += 8) Ss[t * SP + m] *= rinv;
        }
        __syncthreads();
        // ---- O[:, c0:c0+32] = P @ V[:, c0:c0+32]   (M=64, N=32, K=64) ----
        {
            const int nt = wrp >> 2;             // 1 n8-tile per warp
            float od[4] = {0.f, 0.f, 0.f, 0.f};
#pragma unroll
            for (int ks = 0; ks < 8; ks++) {
                const int kk = ks * 8;
                const unsigned a0 = cvt_tf32(Ss[r0 * SP + kk + tg]);
                const unsigned a1 = cvt_tf32(Ss[r1 * SP + kk + tg]);
                const unsigned a2 = cvt_tf32(Ss[r0 * SP + kk + tg + 4]);
                const unsigned a3 = cvt_tf32(Ss[r1 * SP + kk + tg + 4]);
                const unsigned b0 = cvt_tf32(V[(kk + tg) * AP + c0 + nt * 8 + g]);
                const unsigned b1 = cvt_tf32(V[(kk + tg + 4) * AP + c0 + nt * 8 + g]);
                mma8(od[0], od[1], od[2], od[3], a0, a1, a2, a3, b0, b1);
            }
            const int j = c0 + nt * 8 + 2 * tg;
            *reinterpret_cast<float2*>(O + r0 * AP + j) = make_float2(od[0], od[1]);
            *reinterpret_cast<float2*>(O + r1 * AP + j) = make_float2(od[2], od[3]);
        }
        __syncthreads();
    }
}

__global__ void __launch_bounds__(NTH, 1) drgn_kernel(
    const float* __restrict__ x, const int* __restrict__ mask,
    const float* __restrict__ hs,
    const float* __restrict__ enc_w, const float* __restrict__ enc_b,
    const float* __restrict__ q1_w, const float* __restrict__ q1_b,
    const float* __restrict__ k1_w, const float* __restrict__ k1_b,
    const float* __restrict__ v1_w, const float* __restrict__ v1_b,
    const float* __restrict__ o1_w, const float* __restrict__ o1_b,
    const float* __restrict__ q2_w, const float* __restrict__ q2_b,
    const float* __restrict__ k2_w, const float* __restrict__ k2_b,
    const float* __restrict__ v2_w, const float* __restrict__ v2_b,
    const float* __restrict__ o2_w, const float* __restrict__ o2_b,
    const float* __restrict__ w_ih, const float* __restrict__ w_hh,
    const float* __restrict__ b_ih, const float* __restrict__ b_hh,
    const float* __restrict__ lin_w, const float* __restrict__ lin_b,
    float* __restrict__ qs_out, float* __restrict__ h3_out, int act)
{
    extern __shared__ char smem_raw[];
    SmemLayout* s = reinterpret_cast<SmemLayout*>(smem_raw);
    const int tid = threadIdx.x;
    const int b   = blockIdx.x;

    // ---- load x tile and mask bitmap ----
    {
        const float* xb = x + (size_t)b * (N_ANT * 64);
        for (int idx = tid; idx < N_ANT * 64; idx += NTH)
            s->B0[(idx >> 6) * AP + (idx & 63)] = xb[idx];
        if (tid < N_ANT) {
            const int* mrow = mask + ((size_t)b * N_ANT + tid) * N_ANT;
            u64 bits = 0ULL;
            for (int m = 0; m < N_ANT; m++)
                bits |= (u64)(mrow[m] != 0) << m;
            s->mb[tid] = bits;
        }
    }
    // (gemm_one's staging __syncthreads orders the fills above before A reads)

    // ---- encoder: xe = relu(x @ enc_w^T) -> B1 ----
    gemm_one<64>(s->B0, enc_w, enc_b, s->B1, nullptr, nullptr, s->Ws, tid, EPI_RELU);

    // ---- MHA layer 1 (input xe in B1) ----
    gemm_one<128>(s->B1, q1_w, q1_b, s->B0, nullptr, nullptr, s->Ws, tid, EPI_RELU);
    gemm_one<128>(s->B1, k1_w, k1_b, s->B2, nullptr, nullptr, s->Ws, tid, EPI_RELU);
    gemm_one<128>(s->B1, v1_w, v1_b, s->B3, nullptr, nullptr, s->Ws, tid, EPI_RELU);
    attention_mma(s->B0, s->B2, s->B3, s->B1, s->Ss, s->mb, tid);
    gemm_one<128>(s->B1, o1_w, o1_b, s->B0, nullptr, nullptr, s->Ws, tid, EPI_RELU);  // h1 -> B0

    // ---- MHA layer 2 (input h1 in B0) ----
    gemm_one<128>(s->B0, q2_w, q2_b, s->B1, nullptr, nullptr, s->Ws, tid, EPI_RELU);
    gemm_one<128>(s->B0, k2_w, k2_b, s->B2, nullptr, nullptr, s->Ws, tid, EPI_RELU);
    gemm_one<128>(s->B0, v2_w, v2_b, s->B3, nullptr, nullptr, s->Ws, tid, EPI_RELU);
    attention_mma(s->B1, s->B2, s->B3, s->B0, s->Ss, s->mb, tid);
    gemm_one<128>(s->B0, o2_w, o2_b, s->B1, nullptr, nullptr, s->Ws, tid, EPI_RELU);  // h2 -> B1

    // ---- load previous hidden state -> B2 ----
    {
        const float* hb = hs + (size_t)b * (N_ANT * HID);
        for (int idx = tid; idx < N_ANT * HID; idx += NTH)
            s->B2[(idx >> 7) * AP + (idx & 127)] = hb[idx];
    }

    // ---- GRU cell: h2 (B1), h (B2) ----
    gemm_one<128>(s->B1, w_ih,             b_ih,       s->B0, nullptr, nullptr, s->Ws, tid, EPI_PLAIN);   // i_r
    gemm_one<128>(s->B1, w_ih + 128 * HID, b_ih + 128, s->B3, nullptr, nullptr, s->Ws, tid, EPI_PLAIN);   // i_z
    gemm_one<128>(s->B1, w_ih + 256 * HID, b_ih + 256, s->B1, nullptr, nullptr, s->Ws, tid, EPI_PLAIN);   // i_n (in place)
    gemm_one<128>(s->B2, w_hh,             b_hh,       s->B0, s->B0,  nullptr,  s->Ws, tid, EPI_SIGADD);  // r
    gemm_one<128>(s->B2, w_hh + 128 * HID, b_hh + 128, s->B3, s->B3,  nullptr,  s->Ws, tid, EPI_SIGADD);  // z
    gemm_one<128>(s->B2, w_hh + 256 * HID, b_hh + 256, s->B1, s->B1,  s->B0,    s->Ws, tid, EPI_TANHN);   // n

    // ---- h3 = (1-z)*n + z*h ; write h3 to gmem and keep in B1 ----
    {
        float* h3b = h3_out + (size_t)b * (N_ANT * HID);
        for (int idx = tid; idx < N_ANT * HID; idx += NTH) {
            const int off = (idx >> 7) * AP + (idx & 127);
            const float z  = s->B3[off];
            const float h3 = (1.f - z) * s->B1[off] + z * s->B2[off];
            s->B1[off] = h3;
            h3b[idx]   = h3;
        }
    }
    __syncthreads();

    // ---- qs = h3 @ lin_w^T + lin_b ----
    {
        float* qb = qs_out + (size_t)b * (N_ANT * act);
        for (int idx = tid; idx < N_ANT * act; idx += NTH) {
            const int t = idx / act;
            const int a = idx - t * act;
            const float* wr = lin_w + a * HID;
            const float* hr = s->B1 + t * AP;
            float sacc = lin_b[a];
#pragma unroll 8
            for (int k = 0; k < HID; k += 4) {
                const float4 h4 = *reinterpret_cast<const float4*>(hr + k);
                const float4 w4 = *reinterpret_cast<const float4*>(wr + k);
                sacc = fmaf(h4.x, w4.x, sacc);
                sacc = fmaf(h4.y, w4.y, sacc);
                sacc = fmaf(h4.z, w4.z, sacc);
                sacc = fmaf(h4.w, w4.w, sacc);
            }
            qb[idx] = sacc;
        }
    }
}

extern "C" void kernel_launch(void* const* d_in, const int* in_sizes, int n_in,
                              void* d_out, int out_size)
{
    const float* x     = (const float*)d_in[0];
    const int*   mask  = (const int*)  d_in[1];
    const float* hs    = (const float*)d_in[2];
    const float* enc_w = (const float*)d_in[3];
    const float* enc_b = (const float*)d_in[4];
    const float* q1_w  = (const float*)d_in[5];
    const float* q1_b  = (const float*)d_in[6];
    const float* k1_w  = (const float*)d_in[7];
    const float* k1_b  = (const float*)d_in[8];
    const float* v1_w  = (const float*)d_in[9];
    const float* v1_b  = (const float*)d_in[10];
    const float* o1_w  = (const float*)d_in[11];
    const float* o1_b  = (const float*)d_in[12];
    const float* q2_w  = (const float*)d_in[13];
    const float* q2_b  = (const float*)d_in[14];
    const float* k2_w  = (const float*)d_in[15];
    const float* k2_b  = (const float*)d_in[16];
    const float* v2_w  = (const float*)d_in[17];
    const float* v2_b  = (const float*)d_in[18];
    const float* o2_w  = (const float*)d_in[19];
    const float* o2_b  = (const float*)d_in[20];
    const float* w_ih  = (const float*)d_in[21];
    const float* w_hh  = (const float*)d_in[22];
    const float* b_ih  = (const float*)d_in[23];
    const float* b_hh  = (const float*)d_in[24];
    const float* lin_w = (const float*)d_in[25];
    const float* lin_b = (const float*)d_in[26];

    const int bs  = in_sizes[0] / (N_ANT * 64);
    const int act = in_sizes[25] / HID;  // 20

    float* qs = (float*)d_out;
    float* h3 = qs + (size_t)bs * N_ANT * act;

    const int smem_bytes = (int)sizeof(SmemLayout);
    cudaFuncSetAttribute(drgn_kernel, cudaFuncAttributeMaxDynamicSharedMemorySize, smem_bytes);

    drgn_kernel<<<bs, NTH, smem_bytes>>>(
        x, mask, hs, enc_w, enc_b,
        q1_w, q1_b, k1_w, k1_b, v1_w, v1_b, o1_w, o1_b,
        q2_w, q2_b, k2_w, k2_b, v2_w, v2_b, o2_w, o2_b,
        w_ih, w_hh, b_ih, b_hh, lin_w, lin_b,
        qs, h3, act);
}

// round 12
// speedup vs baseline: 1.5562x; 1.0583x over previous
#include <cuda_runtime.h>
#include <math.h>

#define N_ANT 64
#define HID   128
#define AP    132   // activation pitch: (4g+tg) bank map -> A-fragment LDS conflict-free
#define WPF   132   // full-weight pitch: B-fragment loads conflict-free
#define SP    68    // score pitch
#define NTH   512

typedef unsigned long long u64;

__device__ __forceinline__ unsigned cvt_tf32(float v) {
    unsigned r; asm("cvt.rna.tf32.f32 %0, %1;" : "=r"(r) : "f"(v)); return r;
}
__device__ __forceinline__ void mma8(float& d0, float& d1, float& d2, float& d3,
                                     unsigned a0, unsigned a1, unsigned a2, unsigned a3,
                                     unsigned b0, unsigned b1) {
    asm("mma.sync.aligned.m16n8k8.row.col.f32.tf32.tf32.f32 "
        "{%0,%1,%2,%3},{%4,%5,%6,%7},{%8,%9},{%0,%1,%2,%3};"
        : "+f"(d0), "+f"(d1), "+f"(d2), "+f"(d3)
        : "r"(a0), "r"(a1), "r"(a2), "r"(a3), "r"(b0), "r"(b1));
}

struct __align__(16) SmemLayout {
    float B0[N_ANT * AP];
    float B1[N_ANT * AP];
    float B2[N_ANT * AP];
    float B3[N_ANT * AP];
    float Ws[HID * WPF];     // one full weight matrix, tf32-rounded at staging
    float Ss[N_ANT * SP];
    u64   mb[N_ANT];
};

#define EPI_PLAIN  0
#define EPI_RELU   1
#define EPI_SIGADD 2   // C = sigmoid(acc + T)
#define EPI_TANHN  3   // C = tanh(T + R*acc)

// C[64][128] = epi( A[64][KDIM] @ Wg[128][KDIM]^T + bg ), tf32 mma.sync.
// Weights staged coalesced + tf32-rounded ONCE; mainloop loads raw bits (no cvt).
// NOTE: no trailing barrier — the post-mainloop barrier separates this GEMM's
// Ws/A reads from the next GEMM's staging STS; callers that read C outside a
// following gemm_one must sync first.
template <int KDIM>
__device__ __noinline__ void gemm_one(
    const float* __restrict__ A, const float* __restrict__ Wg,
    const float* __restrict__ bg, float* __restrict__ C,
    const float* __restrict__ T, const float* __restrict__ R,
    float* __restrict__ Ws, int tid, int mode)
{
    const int lane = tid & 31;
    const int wrp  = tid >> 5;
    const int g    = lane >> 2;
    const int tg   = lane & 3;
    const int mi   = wrp & 3;
    const int ni   = wrp >> 2;
    const int r0   = mi * 16 + g;
    const int r1   = r0 + 8;

    // ---- stage full weight, coalesced, rounding to tf32 at the store ----
    constexpr int C4 = KDIM / 4;                 // float4 per weight row
    constexpr int IT = (HID * KDIM / 4) / NTH;   // float4 per thread (8 or 4)
    {
        float4 tmp[IT];
#pragma unroll
        for (int i = 0; i < IT; i++) {
            const int f   = tid + i * NTH;
            const int row = f / C4;
            const int c4  = f - row * C4;
            tmp[i] = *reinterpret_cast<const float4*>(Wg + row * KDIM + c4 * 4);
        }
#pragma unroll
        for (int i = 0; i < IT; i++) {
            const int f   = tid + i * NTH;
            const int row = f / C4;
            const int c4  = f - row * C4;
            uint4 u;
            u.x = cvt_tf32(tmp[i].x); u.y = cvt_tf32(tmp[i].y);
            u.z = cvt_tf32(tmp[i].z); u.w = cvt_tf32(tmp[i].w);
            *reinterpret_cast<uint4*>(Ws + row * WPF + c4 * 4) = u;
        }
    }

    // D fragments, bias-initialized: cols j = ni*32+nt*8+2tg, j+1; rows r0, r1
    float d[4][4];
#pragma unroll
    for (int nt = 0; nt < 4; nt++) {
        const float2 b2 = *reinterpret_cast<const float2*>(bg + ni * 32 + nt * 8 + 2 * tg);
        d[nt][0] = b2.x; d[nt][1] = b2.y;
        d[nt][2] = b2.x; d[nt][3] = b2.y;
    }

    __syncthreads();   // Ws staged; also orders prior epilogue/attention writes to A

#pragma unroll 4
    for (int ks = 0; ks < KDIM / 8; ks++) {
        const int kk = ks * 8;
        const unsigned a0 = cvt_tf32(A[r0 * AP + kk + tg]);
        const unsigned a1 = cvt_tf32(A[r1 * AP + kk + tg]);
        const unsigned a2 = cvt_tf32(A[r0 * AP + kk + tg + 4]);
        const unsigned a3 = cvt_tf32(A[r1 * AP + kk + tg + 4]);
#pragma unroll
        for (int nt = 0; nt < 4; nt++) {
            const int n = ni * 32 + nt * 8 + g;
            const unsigned b0 = __float_as_uint(Ws[n * WPF + kk + tg]);
            const unsigned b1 = __float_as_uint(Ws[n * WPF + kk + tg + 4]);
            mma8(d[nt][0], d[nt][1], d[nt][2], d[nt][3], a0, a1, a2, a3, b0, b1);
        }
    }
    __syncthreads();   // all Ws/A reads done -> in-place C safe; next staging safe

#pragma unroll
    for (int nt = 0; nt < 4; nt++) {
        const int j = ni * 32 + nt * 8 + 2 * tg;
        float v0 = d[nt][0], v1 = d[nt][1];
        float v2 = d[nt][2], v3 = d[nt][3];
        if (mode == EPI_RELU) {
            v0 = fmaxf(v0, 0.f); v1 = fmaxf(v1, 0.f);
            v2 = fmaxf(v2, 0.f); v3 = fmaxf(v3, 0.f);
        } else if (mode == EPI_SIGADD) {
            v0 += T[r0 * AP + j]; v1 += T[r0 * AP + j + 1];
            v2 += T[r1 * AP + j]; v3 += T[r1 * AP + j + 1];
            v0 = 1.f / (1.f + __expf(-v0)); v1 = 1.f / (1.f + __expf(-v1));
            v2 = 1.f / (1.f + __expf(-v2)); v3 = 1.f / (1.f + __expf(-v3));
        } else if (mode == EPI_TANHN) {
            v0 = tanhf(T[r0 * AP + j]     + R[r0 * AP + j]     * v0);
            v1 = tanhf(T[r0 * AP + j + 1] + R[r0 * AP + j + 1] * v1);
            v2 = tanhf(T[r1 * AP + j]     + R[r1 * AP + j]     * v2);
            v3 = tanhf(T[r1 * AP + j + 1] + R[r1 * AP + j + 1] * v3);
        }
        *reinterpret_cast<float2*>(C + r0 * AP + j) = make_float2(v0, v1);
        *reinterpret_cast<float2*>(C + r1 * AP + j) = make_float2(v2, v3);
    }
    // no trailing sync (see header comment)
}

// Masked MHA core on tf32 mma. Opens with a barrier: the preceding projection
// epilogues have no trailing sync.
__device__ __noinline__ void attention_mma(
    const float* __restrict__ Q, const float* __restrict__ K,
    const float* __restrict__ V, float* __restrict__ O,
    float* __restrict__ Ss, const u64* __restrict__ mb, int tid)
{
    const float scale = 0.17677669529663687f;  // 1/sqrt(32)
    const int lane = tid & 31;
    const int wrp  = tid >> 5;
    const int g    = lane >> 2;
    const int tg   = lane & 3;
    const int mi   = wrp & 3;
    const int r0   = mi * 16 + g;
    const int r1   = r0 + 8;
    __syncthreads();   // Q/K/V epilogue writes visible
#pragma unroll 1
    for (int h = 0; h < 4; h++) {
        const int c0 = h * 32;
        // ---- scores: S = scale * Q_h @ K_h^T   (M=64, N=64, K=32) ----
        {
            const int nj = wrp >> 2;             // 2 n8-tiles at nj*16
            float sd[2][4] = {{0.f,0.f,0.f,0.f},{0.f,0.f,0.f,0.f}};
#pragma unroll
            for (int ks = 0; ks < 4; ks++) {
                const int kk = c0 + ks * 8;
                const unsigned a0 = cvt_tf32(Q[r0 * AP + kk + tg]);
                const unsigned a1 = cvt_tf32(Q[r1 * AP + kk + tg]);
                const unsigned a2 = cvt_tf32(Q[r0 * AP + kk + tg + 4]);
                const unsigned a3 = cvt_tf32(Q[r1 * AP + kk + tg + 4]);
#pragma unroll
                for (int u = 0; u < 2; u++) {
                    const int n0 = nj * 16 + u * 8;
                    const unsigned b0 = cvt_tf32(K[(n0 + g) * AP + kk + tg]);
                    const unsigned b1 = cvt_tf32(K[(n0 + g) * AP + kk + tg + 4]);
                    mma8(sd[u][0], sd[u][1], sd[u][2], sd[u][3], a0, a1, a2, a3, b0, b1);
                }
            }
#pragma unroll
            for (int u = 0; u < 2; u++) {
                const int n = nj * 16 + u * 8 + 2 * tg;
                Ss[r0 * SP + n]     = sd[u][0] * scale;
                Ss[r0 * SP + n + 1] = sd[u][1] * scale;
                Ss[r1 * SP + n]     = sd[u][2] * scale;
                Ss[r1 * SP + n + 1] = sd[u][3] * scale;
            }
        }
        __syncthreads();
        // ---- masked softmax over keys (8 threads per row) ----
        {
            const int t = tid >> 3;
            const int q = tid & 7;
            const u64 bits = mb[t];
            float mx = -1e30f;
            for (int m = q; m < N_ANT; m += 8)
                if ((bits >> m) & 1ULL) mx = fmaxf(mx, Ss[t * SP + m]);
            mx = fmaxf(mx, __shfl_xor_sync(0xffffffffu, mx, 1));
            mx = fmaxf(mx, __shfl_xor_sync(0xffffffffu, mx, 2));
            mx = fmaxf(mx, __shfl_xor_sync(0xffffffffu, mx, 4));
            float sum = 0.f;
            for (int m = q; m < N_ANT; m += 8) {
                const float p = ((bits >> m) & 1ULL) ? __expf(Ss[t * SP + m] - mx) : 0.f;
                Ss[t * SP + m] = p;
                sum += p;
            }
            sum += __shfl_xor_sync(0xffffffffu, sum, 1);
            sum += __shfl_xor_sync(0xffffffffu, sum, 2);
            sum += __shfl_xor_sync(0xffffffffu, sum, 4);
            const float rinv = 1.f / sum;
            for (int m = q; m < N_ANT; m += 8) Ss[t * SP + m] *= rinv;
        }
        __syncthreads();
        // ---- O[:, c0:c0+32] = P @ V[:, c0:c0+32]   (M=64, N=32, K=64) ----
        {
            const int nt = wrp >> 2;             // 1 n8-tile per warp
            float od[4] = {0.f, 0.f, 0.f, 0.f};
#pragma unroll
            for (int ks = 0; ks < 8; ks++) {
                const int kk = ks * 8;
                const unsigned a0 = cvt_tf32(Ss[r0 * SP + kk + tg]);
                const unsigned a1 = cvt_tf32(Ss[r1 * SP + kk + tg]);
                const unsigned a2 = cvt_tf32(Ss[r0 * SP + kk + tg + 4]);
                const unsigned a3 = cvt_tf32(Ss[r1 * SP + kk + tg + 4]);
                const unsigned b0 = cvt_tf32(V[(kk + tg) * AP + c0 + nt * 8 + g]);
                const unsigned b1 = cvt_tf32(V[(kk + tg + 4) * AP + c0 + nt * 8 + g]);
                mma8(od[0], od[1], od[2], od[3], a0, a1, a2, a3, b0, b1);
            }
            const int j = c0 + nt * 8 + 2 * tg;
            *reinterpret_cast<float2*>(O + r0 * AP + j) = make_float2(od[0], od[1]);
            *reinterpret_cast<float2*>(O + r1 * AP + j) = make_float2(od[2], od[3]);
        }
        __syncthreads();
    }
}

__global__ void __launch_bounds__(NTH, 1) drgn_kernel(
    const float* __restrict__ x, const int* __restrict__ mask,
    const float* __restrict__ hs,
    const float* __restrict__ enc_w, const float* __restrict__ enc_b,
    const float* __restrict__ q1_w, const float* __restrict__ q1_b,
    const float* __restrict__ k1_w, const float* __restrict__ k1_b,
    const float* __restrict__ v1_w, const float* __restrict__ v1_b,
    const float* __restrict__ o1_w, const float* __restrict__ o1_b,
    const float* __restrict__ q2_w, const float* __restrict__ q2_b,
    const float* __restrict__ k2_w, const float* __restrict__ k2_b,
    const float* __restrict__ v2_w, const float* __restrict__ v2_b,
    const float* __restrict__ o2_w, const float* __restrict__ o2_b,
    const float* __restrict__ w_ih, const float* __restrict__ w_hh,
    const float* __restrict__ b_ih, const float* __restrict__ b_hh,
    const float* __restrict__ lin_w, const float* __restrict__ lin_b,
    float* __restrict__ qs_out, float* __restrict__ h3_out, int act)
{
    extern __shared__ char smem_raw[];
    SmemLayout* s = reinterpret_cast<SmemLayout*>(smem_raw);
    const int tid = threadIdx.x;
    const int b   = blockIdx.x;

    // ---- load x tile and mask bitmap ----
    {
        const float* xb = x + (size_t)b * (N_ANT * 64);
        for (int idx = tid; idx < N_ANT * 64; idx += NTH)
            s->B0[(idx >> 6) * AP + (idx & 63)] = xb[idx];
        if (tid < N_ANT) {
            const int* mrow = mask + ((size_t)b * N_ANT + tid) * N_ANT;
            u64 bits = 0ULL;
            for (int m = 0; m < N_ANT; m++)
                bits |= (u64)(mrow[m] != 0) << m;
            s->mb[tid] = bits;
        }
    }
    // (gemm_one's staging __syncthreads orders the fills above before A reads)

    // ---- encoder: xe = relu(x @ enc_w^T) -> B1 ----
    gemm_one<64>(s->B0, enc_w, enc_b, s->B1, nullptr, nullptr, s->Ws, tid, EPI_RELU);

    // ---- MHA layer 1 (input xe in B1) ----
    gemm_one<128>(s->B1, q1_w, q1_b, s->B0, nullptr, nullptr, s->Ws, tid, EPI_RELU);
    gemm_one<128>(s->B1, k1_w, k1_b, s->B2, nullptr, nullptr, s->Ws, tid, EPI_RELU);
    gemm_one<128>(s->B1, v1_w, v1_b, s->B3, nullptr, nullptr, s->Ws, tid, EPI_RELU);
    attention_mma(s->B0, s->B2, s->B3, s->B1, s->Ss, s->mb, tid);
    gemm_one<128>(s->B1, o1_w, o1_b, s->B0, nullptr, nullptr, s->Ws, tid, EPI_RELU);  // h1 -> B0

    // ---- MHA layer 2 (input h1 in B0) ----
    gemm_one<128>(s->B0, q2_w, q2_b, s->B1, nullptr, nullptr, s->Ws, tid, EPI_RELU);
    gemm_one<128>(s->B0, k2_w, k2_b, s->B2, nullptr, nullptr, s->Ws, tid, EPI_RELU);
    gemm_one<128>(s->B0, v2_w, v2_b, s->B3, nullptr, nullptr, s->Ws, tid, EPI_RELU);
    attention_mma(s->B1, s->B2, s->B3, s->B0, s->Ss, s->mb, tid);
    gemm_one<128>(s->B0, o2_w, o2_b, s->B1, nullptr, nullptr, s->Ws, tid, EPI_RELU);  // h2 -> B1

    // ---- load previous hidden state -> B2 ----
    {
        const float* hb = hs + (size_t)b * (N_ANT * HID);
        for (int idx = tid; idx < N_ANT * HID; idx += NTH)
            s->B2[(idx >> 7) * AP + (idx & 127)] = hb[idx];
    }

    // ---- GRU cell: h2 (B1), h (B2) ----
    gemm_one<128>(s->B1, w_ih,             b_ih,       s->B0, nullptr, nullptr, s->Ws, tid, EPI_PLAIN);   // i_r
    gemm_one<128>(s->B1, w_ih + 128 * HID, b_ih + 128, s->B3, nullptr, nullptr, s->Ws, tid, EPI_PLAIN);   // i_z
    gemm_one<128>(s->B1, w_ih + 256 * HID, b_ih + 256, s->B1, nullptr, nullptr, s->Ws, tid, EPI_PLAIN);   // i_n (in place)
    gemm_one<128>(s->B2, w_hh,             b_hh,       s->B0, s->B0,  nullptr,  s->Ws, tid, EPI_SIGADD);  // r
    gemm_one<128>(s->B2, w_hh + 128 * HID, b_hh + 128, s->B3, s->B3,  nullptr,  s->Ws, tid, EPI_SIGADD);  // z
    gemm_one<128>(s->B2, w_hh + 256 * HID, b_hh + 256, s->B1, s->B1,  s->B0,    s->Ws, tid, EPI_TANHN);   // n

    __syncthreads();   // z/n epilogue writes visible before the combine

    // ---- h3 = (1-z)*n + z*h ; write h3 to gmem and keep in B1 ----
    {
        float* h3b = h3_out + (size_t)b * (N_ANT * HID);
        for (int idx = tid; idx < N_ANT * HID; idx += NTH) {
            const int off = (idx >> 7) * AP + (idx & 127);
            const float z  = s->B3[off];
            const float h3 = (1.f - z) * s->B1[off] + z * s->B2[off];
            s->B1[off] = h3;
            h3b[idx]   = h3;
        }
    }
    __syncthreads();

    // ---- qs = h3 @ lin_w^T + lin_b ----
    {
        float* qb = qs_out + (size_t)b * (N_ANT * act);
        for (int idx = tid; idx < N_ANT * act; idx += NTH) {
            const int t = idx / act;
            const int a = idx - t * act;
            const float* wr = lin_w + a * HID;
            const float* hr = s->B1 + t * AP;
            float sacc = lin_b[a];
#pragma unroll 8
            for (int k = 0; k < HID; k += 4) {
                const float4 h4 = *reinterpret_cast<const float4*>(hr + k);
                const float4 w4 = *reinterpret_cast<const float4*>(wr + k);
                sacc = fmaf(h4.x, w4.x, sacc);
                sacc = fmaf(h4.y, w4.y, sacc);
                sacc = fmaf(h4.z, w4.z, sacc);
                sacc = fmaf(h4.w, w4.w, sacc);
            }
            qb[idx] = sacc;
        }
    }
}

extern "C" void kernel_launch(void* const* d_in, const int* in_sizes, int n_in,
                              void* d_out, int out_size)
{
    const float* x     = (const float*)d_in[0];
    const int*   mask  = (const int*)  d_in[1];
    const float* hs    = (const float*)d_in[2];
    const float* enc_w = (const float*)d_in[3];
    const float* enc_b = (const float*)d_in[4];
    const float* q1_w  = (const float*)d_in[5];
    const float* q1_b  = (const float*)d_in[6];
    const float* k1_w  = (const float*)d_in[7];
    const float* k1_b  = (const float*)d_in[8];
    const float* v1_w  = (const float*)d_in[9];
    const float* v1_b  = (const float*)d_in[10];
    const float* o1_w  = (const float*)d_in[11];
    const float* o1_b  = (const float*)d_in[12];
    const float* q2_w  = (const float*)d_in[13];
    const float* q2_b  = (const float*)d_in[14];
    const float* k2_w  = (const float*)d_in[15];
    const float* k2_b  = (const float*)d_in[16];
    const float* v2_w  = (const float*)d_in[17];
    const float* v2_b  = (const float*)d_in[18];
    const float* o2_w  = (const float*)d_in[19];
    const float* o2_b  = (const float*)d_in[20];
    const float* w_ih  = (const float*)d_in[21];
    const float* w_hh  = (const float*)d_in[22];
    const float* b_ih  = (const float*)d_in[23];
    const float* b_hh  = (const float*)d_in[24];
    const float* lin_w = (const float*)d_in[25];
    const float* lin_b = (const float*)d_in[26];

    const int bs  = in_sizes[0] / (N_ANT * 64);
    const int act = in_sizes[25] / HID;  // 20

    float* qs = (float*)d_out;
    float* h3 = qs + (size_t)bs * N_ANT * act;

    const int smem_bytes = (int)sizeof(SmemLayout);
    cudaFuncSetAttribute(drgn_kernel, cudaFuncAttributeMaxDynamicSharedMemorySize, smem_bytes);

    drgn_kernel<<<bs, NTH, smem_bytes>>>(
        x, mask, hs, enc_w, enc_b,
        q1_w, q1_b, k1_w, k1_b, v1_w, v1_b, o1_w, o1_b,
        q2_w, q2_b, k2_w, k2_b, v2_w, v2_b, o2_w, o2_b,
        w_ih, w_hh, b_ih, b_hh, lin_w, lin_b,
        qs, h3, act);
}